// round 2
// baseline (speedup 1.0000x reference)
#include <cuda_runtime.h>
#include <cstdint>
#include <cstdio>

// LSTMCell: gates = x@Wx + bx + h@Wh ; i,f,g,o -> (h_new, c_new)
// B=8192, I=H=1024, 4H=4096. Single virtual GEMM [8192,2048]x[2048,4096],
// K 0..1023 from (x, Wx), K 1024..2047 from (h, Wh).
// Gate-interleaved N-tiling: block covers 32 columns of EACH gate, so the
// LSTM nonlinearity fuses in the epilogue (no gates scratch buffer).

#define BDIM   8192
#define IDIM   1024
#define HDIM   1024
#define NGATE  4096
#define KTOT   2048

#define BM 128
#define BN 128          // = 32 cols per gate x 4 gates
#define BK 32
#define NKT (KTOT / BK) // 64
#define LDA 36          // BK + 4 pad (floats)
#define LDB 132         // BN + 4 pad (floats)
#define LDE 132         // epilogue tile pad

#define THREADS 256

// smem: GEMM phase: As[2][BM][LDA] (9216 u32) + Bs[2][BK][LDB] (8448 u32)
//       EPI phase:  gsm[BM][LDE]   (16896 f32) -- reuses same memory
#define SMEM_U32 (2*BM*LDA + 2*BK*LDB)   // 17664 u32 = 70656 B
#define SMEM_BYTES (SMEM_U32 * 4)

__device__ __forceinline__ uint32_t f2tf32(float x) {
    uint32_t r;
    asm("cvt.rna.tf32.f32 %0, %1;" : "=r"(r) : "f"(x));
    return r;
}

__device__ __forceinline__ float sigmoidf_(float x) {
    return 1.0f / (1.0f + expf(-x));
}

__global__ __launch_bounds__(THREADS, 1)
void lstm_fused_kernel(const float* __restrict__ x,
                       const float* __restrict__ h,
                       const float* __restrict__ c,
                       const float* __restrict__ Wx,
                       const float* __restrict__ bx,
                       const float* __restrict__ Wh,
                       float* __restrict__ out)
{
    extern __shared__ uint32_t smem[];
    uint32_t* As = smem;                 // [2][BM][LDA]
    uint32_t* Bs = smem + 2 * BM * LDA;  // [2][BK][LDB]
    float*    gsm = (float*)smem;        // [BM][LDE] (reused after GEMM)

    const int tid  = threadIdx.x;
    const int lane = tid & 31;
    const int warp = tid >> 5;
    const int wm   = warp >> 2;   // 0..1 : 64-row slab
    const int wn   = warp & 3;    // 0..3 : 32-col slab

    const int m0 = blockIdx.y * BM;
    const int n0 = blockIdx.x * (BN / 4);   // 32 cols per gate

    float acc[4][4][4];
    #pragma unroll
    for (int i = 0; i < 4; i++)
        #pragma unroll
        for (int j = 0; j < 4; j++)
            #pragma unroll
            for (int k = 0; k < 4; k++) acc[i][j][k] = 0.0f;

    // ---------------- prologue: K-tile 0 straight to smem buf 0 ----------
    {
        #pragma unroll
        for (int i = 0; i < 4; i++) {
            int idx = tid + i * THREADS;       // 0..1023
            int row = idx >> 3, c4 = idx & 7;  // A: 128 rows x 8 float4
            float4 v = *(const float4*)(x + (size_t)(m0 + row) * IDIM + c4 * 4);
            uint32_t* d = &As[row * LDA + c4 * 4];
            d[0] = f2tf32(v.x); d[1] = f2tf32(v.y);
            d[2] = f2tf32(v.z); d[3] = f2tf32(v.w);
        }
        #pragma unroll
        for (int i = 0; i < 4; i++) {
            int idx = tid + i * THREADS;
            int row = idx >> 5, c4 = idx & 31; // B: 32 rows x 32 float4
            int col = (c4 >> 3) * 1024 + n0 + (c4 & 7) * 4; // gate-interleaved
            float4 v = *(const float4*)(Wx + (size_t)row * NGATE + col);
            uint32_t* d = &Bs[row * LDB + c4 * 4];
            d[0] = f2tf32(v.x); d[1] = f2tf32(v.y);
            d[2] = f2tf32(v.z); d[3] = f2tf32(v.w);
        }
    }
    __syncthreads();

    // ---------------- main loop: double-buffered -------------------------
    float4 aN[4], bN[4];
    for (int kt = 0; kt < NKT; kt++) {
        const int cur = kt & 1;

        if (kt + 1 < NKT) {
            const int k0 = (kt + 1) * BK;
            const float* Asrc; const float* Wsrc; int kk;
            if (k0 < 1024) { Asrc = x; Wsrc = Wx; kk = k0; }
            else           { Asrc = h; Wsrc = Wh; kk = k0 - 1024; }
            #pragma unroll
            for (int i = 0; i < 4; i++) {
                int idx = tid + i * THREADS;
                int row = idx >> 3, c4 = idx & 7;
                aN[i] = *(const float4*)(Asrc + (size_t)(m0 + row) * IDIM + kk + c4 * 4);
            }
            #pragma unroll
            for (int i = 0; i < 4; i++) {
                int idx = tid + i * THREADS;
                int row = idx >> 5, c4 = idx & 31;
                int col = (c4 >> 3) * 1024 + n0 + (c4 & 7) * 4;
                bN[i] = *(const float4*)(Wsrc + (size_t)(kk + row) * NGATE + col);
            }
        }

        // compute on buffer `cur`
        const uint32_t* Ab = As + cur * BM * LDA;
        const uint32_t* Bb = Bs + cur * BK * LDB;
        const int r = lane >> 2, cc = lane & 3;
        #pragma unroll
        for (int ks = 0; ks < 4; ks++) {
            uint32_t af[4][4];
            #pragma unroll
            for (int mt = 0; mt < 4; mt++) {
                int m  = wm * 64 + mt * 16 + r;
                int kb = ks * 8 + cc;
                af[mt][0] = Ab[m * LDA + kb];
                af[mt][1] = Ab[(m + 8) * LDA + kb];
                af[mt][2] = Ab[m * LDA + kb + 4];
                af[mt][3] = Ab[(m + 8) * LDA + kb + 4];
            }
            uint32_t bf[4][2];
            #pragma unroll
            for (int nt = 0; nt < 4; nt++) {
                int n = wn * 32 + nt * 8 + r;
                bf[nt][0] = Bb[(ks * 8 + cc) * LDB + n];
                bf[nt][1] = Bb[(ks * 8 + cc + 4) * LDB + n];
            }
            #pragma unroll
            for (int mt = 0; mt < 4; mt++)
                #pragma unroll
                for (int nt = 0; nt < 4; nt++) {
                    asm volatile(
                        "mma.sync.aligned.m16n8k8.row.col.f32.tf32.tf32.f32 "
                        "{%0,%1,%2,%3}, {%4,%5,%6,%7}, {%8,%9}, {%0,%1,%2,%3};"
                        : "+f"(acc[mt][nt][0]), "+f"(acc[mt][nt][1]),
                          "+f"(acc[mt][nt][2]), "+f"(acc[mt][nt][3])
                        : "r"(af[mt][0]), "r"(af[mt][1]),
                          "r"(af[mt][2]), "r"(af[mt][3]),
                          "r"(bf[nt][0]), "r"(bf[nt][1]));
                }
        }

        if (kt + 1 < NKT) {
            const int nxt = cur ^ 1;
            uint32_t* Ad = As + nxt * BM * LDA;
            uint32_t* Bd = Bs + nxt * BK * LDB;
            #pragma unroll
            for (int i = 0; i < 4; i++) {
                int idx = tid + i * THREADS;
                int row = idx >> 3, c4 = idx & 7;
                uint32_t* d = &Ad[row * LDA + c4 * 4];
                d[0] = f2tf32(aN[i].x); d[1] = f2tf32(aN[i].y);
                d[2] = f2tf32(aN[i].z); d[3] = f2tf32(aN[i].w);
            }
            #pragma unroll
            for (int i = 0; i < 4; i++) {
                int idx = tid + i * THREADS;
                int row = idx >> 5, c4 = idx & 31;
                uint32_t* d = &Bd[row * LDB + c4 * 4];
                d[0] = f2tf32(bN[i].x); d[1] = f2tf32(bN[i].y);
                d[2] = f2tf32(bN[i].z); d[3] = f2tf32(bN[i].w);
            }
        }
        __syncthreads();  // also fences last iteration before smem reuse
    }

    // ---------------- epilogue: regroup via smem, fuse LSTM --------------
    {
        const int r = lane >> 2, cc = lane & 3;
        #pragma unroll
        for (int mt = 0; mt < 4; mt++) {
            #pragma unroll
            for (int nt = 0; nt < 4; nt++) {
                int row = wm * 64 + mt * 16 + r;
                int col = wn * 32 + nt * 8 + cc * 2;
                *(float2*)&gsm[row * LDE + col] =
                    make_float2(acc[mt][nt][0], acc[mt][nt][1]);
                *(float2*)&gsm[(row + 8) * LDE + col] =
                    make_float2(acc[mt][nt][2], acc[mt][nt][3]);
            }
        }
    }
    __syncthreads();

    float* out_h = out;
    float* out_c = out + (size_t)BDIM * HDIM;
    #pragma unroll
    for (int i = 0; i < 16; i++) {
        int o   = tid + i * THREADS;   // 0..4095
        int row = o >> 5;
        int j   = o & 31;
        float gi = gsm[row * LDE + j]      + bx[n0 + j];
        float gf = gsm[row * LDE + 32 + j] + bx[1024 + n0 + j];
        float gg = gsm[row * LDE + 64 + j] + bx[2048 + n0 + j];
        float go = gsm[row * LDE + 96 + j] + bx[3072 + n0 + j];
        float iv = sigmoidf_(gi);
        float fv = sigmoidf_(gf);
        float gv = tanhf(gg);
        float ov = sigmoidf_(go);
        size_t gidx = (size_t)(m0 + row) * HDIM + n0 + j;
        float cn = fv * c[gidx] + iv * gv;
        out_h[gidx] = ov * tanhf(cn);
        out_c[gidx] = cn;
    }
}

extern "C" void kernel_launch(void* const* d_in, const int* in_sizes, int n_in,
                              void* d_out, int out_size)
{
    const float* x  = (const float*)d_in[0];
    const float* h  = (const float*)d_in[1];
    const float* c  = (const float*)d_in[2];
    const float* Wx = (const float*)d_in[3];
    const float* bx = (const float*)d_in[4];
    const float* Wh = (const float*)d_in[5];
    float* out = (float*)d_out;

    cudaFuncSetAttribute(lstm_fused_kernel,
                         cudaFuncAttributeMaxDynamicSharedMemorySize, SMEM_BYTES);

    dim3 grid(NGATE / BN, BDIM / BM);   // (32, 64)
    lstm_fused_kernel<<<grid, THREADS, SMEM_BYTES>>>(x, h, c, Wx, bx, Wh, out);
}

// round 7
// speedup vs baseline: 3.3960x; 3.3960x over previous
#include <cuda_runtime.h>
#include <cuda_fp16.h>
#include <cstdint>

// LSTMCell: gates = x@Wx + bx + h@Wh ; i,f,g,o -> (h_new, c_new)
// B=8192, I=H=1024. Virtual GEMM [8192,2048] x [2048,4096]^T (fp16, f32 acc).
// Pre-pass 1: g_Ah[8192,2048] fp16 = concat(x,h), K-major.
// Pre-pass 2: g_Wt[4096,2048] fp16 = W^T, K-major, rows gate-interleaved
//             (row j*4+g = gate g, unit j) so the LSTM epilogue fuses per CTA.
// Main: 128x128 tile per CTA, cp.async 3-stage pipeline, ldmatrix.x4 feed,
//       mma.sync.m16n8k16.f16, smem regroup + fused LSTM epilogue.

#define B_DIM 8192
#define K_DIM 2048
#define N_DIM 4096
#define H_DIM 1024

#define BM 128
#define BN 128
#define BKH 64                    // K-chunk in halves = 128 B rows
#define NCHUNK (K_DIM / BKH)      // 32
#define THREADS 256
#define STAGES 3

#define STAGE_BYTES (BM * 128 + BN * 128)       // 32768
#define OFF_BIAS (STAGES * STAGE_BYTES)         // 98304
#define SMEM_TOTAL (OFF_BIAS + BN * 4)          // 98816
#define LDE 132                                  // epilogue row pitch (floats)

__device__ __half g_Ah[(size_t)B_DIM * K_DIM];  // 32 MB
__device__ __half g_Wt[(size_t)N_DIM * K_DIM];  // 16 MB

#define SW128(o) ((o) ^ (((o) >> 3) & 0x70))

__device__ __forceinline__ uint32_t smem_u32(const void* p) {
    uint32_t a;
    asm("{ .reg .u64 t; cvta.to.shared.u64 t, %1; cvt.u32.u64 %0, t; }"
        : "=r"(a) : "l"(p));
    return a;
}

__device__ __forceinline__ void cp16(uint32_t dst, const void* src) {
    asm volatile("cp.async.cg.shared.global [%0], [%1], 16;"
                 :: "r"(dst), "l"(src) : "memory");
}
#define CP_COMMIT() asm volatile("cp.async.commit_group;" ::: "memory")

__device__ __forceinline__ void ldsm4(uint32_t& r0, uint32_t& r1,
                                      uint32_t& r2, uint32_t& r3, uint32_t a) {
    asm volatile("ldmatrix.sync.aligned.m8n8.x4.shared.b16 {%0,%1,%2,%3}, [%4];"
                 : "=r"(r0), "=r"(r1), "=r"(r2), "=r"(r3) : "r"(a));
}

// ------------------------------------------------------------- pre-passes
__global__ void conv_A(const float* __restrict__ x, const float* __restrict__ h) {
    int i = blockIdx.x * blockDim.x + threadIdx.x;   // B*K/8 threads
    int row = i >> 8;
    int col = (i & 255) * 8;
    const float* src = (col < 1024) ? (x + (size_t)row * 1024 + col)
                                    : (h + (size_t)row * 1024 + (col - 1024));
    float4 v0 = ((const float4*)src)[0];
    float4 v1 = ((const float4*)src)[1];
    __half2 p[4];
    p[0] = __floats2half2_rn(v0.x, v0.y);
    p[1] = __floats2half2_rn(v0.z, v0.w);
    p[2] = __floats2half2_rn(v1.x, v1.y);
    p[3] = __floats2half2_rn(v1.z, v1.w);
    *(uint4*)(g_Ah + (size_t)row * K_DIM + col) = *(uint4*)p;
}

__global__ void transpose_W(const float* __restrict__ Wx, const float* __restrict__ Wh) {
    __shared__ __half t[32][36];
    int g = blockIdx.z;
    int j0 = blockIdx.x * 32, k0 = blockIdx.y * 32;
    int tx = threadIdx.x, ty = threadIdx.y;          // 32 x 8
    #pragma unroll
    for (int i = 0; i < 4; i++) {
        int k = k0 + ty + i * 8;
        const float* src = (k < 1024) ? (Wx + (size_t)k * N_DIM)
                                      : (Wh + (size_t)(k - 1024) * N_DIM);
        t[ty + i * 8][tx] = __float2half_rn(src[g * 1024 + j0 + tx]);
    }
    __syncthreads();
    #pragma unroll
    for (int i = 0; i < 4; i++) {
        int jj = ty + i * 8;
        g_Wt[((size_t)(j0 + jj) * 4 + g) * K_DIM + k0 + tx] = t[tx][jj];
    }
}

// ------------------------------------------------------------- main kernel
__global__ __launch_bounds__(THREADS, 2)
void lstm_main(const float* __restrict__ cin, const float* __restrict__ bx,
               float* __restrict__ out)
{
    extern __shared__ char smem[];
    const uint32_t sb = smem_u32(smem);
    const int tid  = threadIdx.x;
    const int lane = tid & 31;
    const int warp = tid >> 5;
    const int wm   = warp >> 2;       // 0..1  (64-row slab)
    const int wn   = warp & 3;        // 0..3  (32-col slab)
    const int m0 = blockIdx.y * BM;
    const int n0 = blockIdx.x * BN;
    const int jt0 = n0 >> 2;

    const int r0 = tid >> 3, c8 = tid & 7;   // copy: 32 rows x 8 x 16B

    const __half* Agm = g_Ah + (size_t)m0 * K_DIM;
    const __half* Bgm = g_Wt + (size_t)n0 * K_DIM;

    float acc[4][4][4];
    #pragma unroll
    for (int i = 0; i < 4; i++)
        #pragma unroll
        for (int j = 0; j < 4; j++)
            #pragma unroll
            for (int k = 0; k < 4; k++) acc[i][j][k] = 0.0f;

    // -- pipeline prologue: chunks 0,1 ------------------------------------
    #pragma unroll
    for (int pc = 0; pc < 2; pc++) {
        uint32_t Ab = sb + pc * STAGE_BYTES;
        uint32_t Bb = Ab + BM * 128;
        #pragma unroll
        for (int i = 0; i < 4; i++) {
            int row = r0 + 32 * i;
            uint32_t o = (uint32_t)row * 128 + c8 * 16;
            cp16(Ab + SW128(o), Agm + (size_t)row * K_DIM + pc * BKH + c8 * 8);
            cp16(Bb + SW128(o), Bgm + (size_t)row * K_DIM + pc * BKH + c8 * 8);
        }
        CP_COMMIT();
    }

    // -- main loop --------------------------------------------------------
    for (int kt = 0; kt < NCHUNK; kt++) {
        if (kt + 2 < NCHUNK) {
            const int s = (kt + 2) % STAGES;
            uint32_t Ab = sb + s * STAGE_BYTES;
            uint32_t Bb = Ab + BM * 128;
            const int ko = (kt + 2) * BKH;
            #pragma unroll
            for (int i = 0; i < 4; i++) {
                int row = r0 + 32 * i;
                uint32_t o = (uint32_t)row * 128 + c8 * 16;
                cp16(Ab + SW128(o), Agm + (size_t)row * K_DIM + ko + c8 * 8);
                cp16(Bb + SW128(o), Bgm + (size_t)row * K_DIM + ko + c8 * 8);
            }
            CP_COMMIT();
            asm volatile("cp.async.wait_group 2;" ::: "memory");
        } else if (kt + 1 < NCHUNK) {
            asm volatile("cp.async.wait_group 1;" ::: "memory");
        } else {
            asm volatile("cp.async.wait_group 0;" ::: "memory");
        }
        __syncthreads();

        // compute on stage kt%3
        const uint32_t Ab = sb + (kt % STAGES) * STAGE_BYTES;
        const uint32_t Bb = Ab + BM * 128;
        const int q  = lane >> 3;     // matrix index within ldmatrix.x4
        const int rr = lane & 7;
        #pragma unroll
        for (int ks = 0; ks < 4; ks++) {        // 4 x k16 steps
            uint32_t a[4][4];
            #pragma unroll
            for (int mt = 0; mt < 4; mt++) {
                int row = wm * 64 + mt * 16 + (q & 1) * 8 + rr;
                uint32_t o = (uint32_t)row * 128 + ks * 32 + (q >> 1) * 16;
                ldsm4(a[mt][0], a[mt][1], a[mt][2], a[mt][3], Ab + SW128(o));
            }
            uint32_t b[2][4];
            #pragma unroll
            for (int np = 0; np < 2; np++) {    // 2 n-tiles per ldmatrix.x4
                int row = wn * 32 + np * 16 + (q >> 1) * 8 + rr;
                uint32_t o = (uint32_t)row * 128 + ks * 32 + (q & 1) * 16;
                ldsm4(b[np][0], b[np][1], b[np][2], b[np][3], Bb + SW128(o));
            }
            #pragma unroll
            for (int mt = 0; mt < 4; mt++)
                #pragma unroll
                for (int nt = 0; nt < 4; nt++) {
                    const uint32_t b0 = b[nt >> 1][(nt & 1) * 2];
                    const uint32_t b1 = b[nt >> 1][(nt & 1) * 2 + 1];
                    asm volatile(
                        "mma.sync.aligned.m16n8k16.row.col.f32.f16.f16.f32 "
                        "{%0,%1,%2,%3}, {%4,%5,%6,%7}, {%8,%9}, {%0,%1,%2,%3};"
                        : "+f"(acc[mt][nt][0]), "+f"(acc[mt][nt][1]),
                          "+f"(acc[mt][nt][2]), "+f"(acc[mt][nt][3])
                        : "r"(a[mt][0]), "r"(a[mt][1]),
                          "r"(a[mt][2]), "r"(a[mt][3]),
                          "r"(b0), "r"(b1));
                }
        }
        __syncthreads();   // stage kt%3 free for the copy issued at kt+1
    }

    // -- epilogue: regroup via smem, fuse LSTM ----------------------------
    float* gsm = (float*)smem;        // [128][LDE]
    {
        const int gr = lane >> 2, gc = lane & 3;
        #pragma unroll
        for (int mt = 0; mt < 4; mt++)
            #pragma unroll
            for (int nt = 0; nt < 4; nt++) {
                int row = wm * 64 + mt * 16 + gr;
                int col = wn * 32 + nt * 8 + gc * 2;
                *(float2*)&gsm[row * LDE + col] =
                    make_float2(acc[mt][nt][0], acc[mt][nt][1]);
                *(float2*)&gsm[(row + 8) * LDE + col] =
                    make_float2(acc[mt][nt][2], acc[mt][nt][3]);
            }
    }
    float* bsm = (float*)(smem + OFF_BIAS);
    if (tid < BN)
        bsm[tid] = bx[(tid & 3) * 1024 + jt0 + (tid >> 2)];
    __syncthreads();

    float* outh = out;
    float* outc = out + (size_t)B_DIM * H_DIM;
    #pragma unroll
    for (int i = 0; i < 16; i++) {
        int o   = tid + i * THREADS;   // 0..4095 = 128 rows x 32 units
        int u   = o & 31;
        int row = o >> 5;
        float gi = gsm[row * LDE + u * 4 + 0] + bsm[u * 4 + 0];
        float gf = gsm[row * LDE + u * 4 + 1] + bsm[u * 4 + 1];
        float gg = gsm[row * LDE + u * 4 + 2] + bsm[u * 4 + 2];
        float go = gsm[row * LDE + u * 4 + 3] + bsm[u * 4 + 3];
        float iv = 1.0f / (1.0f + __expf(-gi));
        float fv = 1.0f / (1.0f + __expf(-gf));
        float gv = tanhf(gg);
        float ov = 1.0f / (1.0f + __expf(-go));
        size_t gidx = (size_t)(m0 + row) * H_DIM + jt0 + u;
        float cn = fv * cin[gidx] + iv * gv;
        outh[gidx] = ov * tanhf(cn);
        outc[gidx] = cn;
    }
}

// ------------------------------------------------------------- launch
extern "C" void kernel_launch(void* const* d_in, const int* in_sizes, int n_in,
                              void* d_out, int out_size)
{
    const float* x  = (const float*)d_in[0];
    const float* h  = (const float*)d_in[1];
    const float* c  = (const float*)d_in[2];
    const float* Wx = (const float*)d_in[3];
    const float* bx = (const float*)d_in[4];
    const float* Wh = (const float*)d_in[5];
    float* out = (float*)d_out;

    conv_A<<<(B_DIM * K_DIM / 8) / 256, 256>>>(x, h);
    transpose_W<<<dim3(32, 64, 4), dim3(32, 8)>>>(Wx, Wh);

    cudaFuncSetAttribute(lstm_main,
                         cudaFuncAttributeMaxDynamicSharedMemorySize, SMEM_TOTAL);
    dim3 grid(N_DIM / BN, B_DIM / BM);   // (32, 64)
    lstm_main<<<grid, THREADS, SMEM_TOTAL>>>(c, bx, out);
}